// round 2
// baseline (speedup 1.0000x reference)
#include <cuda_runtime.h>
#include <math.h>

// ---------------------------------------------------------------------------
// RealNVP forward: 6 coupling layers with per-layer batchnorm stats.
// Per layer: stats (2-phase deterministic) -> fused normalize+2xMLP+affine.
// Fused kernel keeps h1 (64x512 fp32) in SMEM; W2 streamed from L2 in
// 64n x 32k panels; 4x4 register microtiles over transposed [k][m] SMEM.
// ---------------------------------------------------------------------------

#define NR       65536
#define DIM      64
#define DH       32
#define HID      512
#define NLAYERS  6
#define TM       64
#define NBLK     (NR / TM)       // 1024
#define LDT      68              // padded smem leading dim ([k][m] layouts)
#define SMEM_BYTES 199936        // see layout below

// Persistent device scratch (static: allocation is forbidden in kernel_launch)
__device__ float g_x[NR * DIM];      // evolving x (16 MB)
__device__ float g_det[NR];          // det_s accumulator
__device__ float g_sp[256 * 64];     // stats partial sums
__device__ float g_sq[256 * 64];     // stats partial sumsq
__device__ float g_mean[DIM];
__device__ float g_rstd[DIM];
__device__ float g_llp[NBLK];        // log-likelihood partials
__device__ float g_detp[NBLK];       // det partials

// ---------------------------------------------------------------------------
// Stats: column mean/var over all 65536 rows, deterministic two-phase.
// ---------------------------------------------------------------------------
__global__ void stats_partial(const float* __restrict__ xext, int use_ext) {
    const float* xin = use_ext ? xext : g_x;
    __shared__ float ssum[4][64], ssq[4][64];
    int tid = threadIdx.x;
    int c = tid & 63, g = tid >> 6;
    int base = blockIdx.x * 256 + g * 64;
    float s = 0.f, q = 0.f;
    for (int i = 0; i < 64; i++) {
        float v = xin[(size_t)(base + i) * DIM + c];
        s += v; q += v * v;
    }
    ssum[g][c] = s; ssq[g][c] = q;
    __syncthreads();
    if (tid < 64) {
        float S = ssum[0][tid] + ssum[1][tid] + ssum[2][tid] + ssum[3][tid];
        float Q = ssq[0][tid] + ssq[1][tid] + ssq[2][tid] + ssq[3][tid];
        g_sp[blockIdx.x * 64 + tid] = S;
        g_sq[blockIdx.x * 64 + tid] = Q;
    }
}

__global__ void stats_final() {
    int c = threadIdx.x;  // 64 threads
    float S = 0.f, Q = 0.f;
    for (int b = 0; b < 256; b++) { S += g_sp[b * 64 + c]; Q += g_sq[b * 64 + c]; }
    float mean = S / (float)NR;
    float var  = Q / (float)NR - mean * mean;
    g_mean[c] = mean;
    g_rstd[c] = 1.0f / sqrtf(var + 1e-5f);
}

// ---------------------------------------------------------------------------
// 64x64 microtile MAC: C[m][n] += sum_k At[k][m] * Wt[k][n], K=32.
// At, Wt in SMEM with leading dim LDT. Thread owns 4 rows x 4 cols.
// ---------------------------------------------------------------------------
__device__ __forceinline__ void mm_tile32(const float* __restrict__ At,
                                          const float* __restrict__ Wt,
                                          float acc[4][4], int m0, int n0) {
#pragma unroll
    for (int k = 0; k < 32; k++) {
        float4 a = *(const float4*)(At + k * LDT + m0);
        float4 b = *(const float4*)(Wt + k * LDT + n0);
        acc[0][0] += a.x * b.x; acc[0][1] += a.x * b.y; acc[0][2] += a.x * b.z; acc[0][3] += a.x * b.w;
        acc[1][0] += a.y * b.x; acc[1][1] += a.y * b.y; acc[1][2] += a.y * b.z; acc[1][3] += a.y * b.w;
        acc[2][0] += a.z * b.x; acc[2][1] += a.z * b.y; acc[2][2] += a.z * b.z; acc[2][3] += a.z * b.w;
        acc[3][0] += a.w * b.x; acc[3][1] += a.w * b.y; acc[3][2] += a.w * b.z; acc[3][3] += a.w * b.w;
    }
}

// ---------------------------------------------------------------------------
// Fused coupling layer: normalize, s-MLP, t-MLP, y2 = x2*exp(s)+t, det_s.
// SMEM layout (floats):
//   xT   [64][68]  normalized x, transposed [col][row]        4352
//   h1T  [512][68] hidden activations, [k][m]                34816
//   wpan [32][68]  staged weight panel, [k][n]                2176
//   h2cT [64][68]  h2 chunk, [n][m]                           4352
//   w3t  [64][34]  W3 panel, [n][j]                           2176
//   sbuf [64][33]  s values for det reduction                 2112
// total 49984 floats = 199936 bytes
// ---------------------------------------------------------------------------
__global__ void __launch_bounds__(256, 1) fused_layer(
    const float* __restrict__ xext, int use_ext, int x1off, int first,
    const float* __restrict__ sW1, const float* __restrict__ sb1,
    const float* __restrict__ sW2, const float* __restrict__ sb2,
    const float* __restrict__ sW3, const float* __restrict__ sb3,
    const float* __restrict__ tW1, const float* __restrict__ tb1,
    const float* __restrict__ tW2, const float* __restrict__ tb2,
    const float* __restrict__ tW3, const float* __restrict__ tb3) {
    extern __shared__ float sm[];
    float* xT   = sm;
    float* h1T  = xT + DIM * LDT;
    float* wpan = h1T + HID * LDT;
    float* h2cT = wpan + 32 * LDT;
    float* w3t  = h2cT + TM * LDT;
    float* sbuf = w3t + 64 * 34;

    const float* xin = use_ext ? xext : g_x;
    int tid = threadIdx.x;
    int mb  = blockIdx.x * TM;
    int ty = tid >> 4, tx = tid & 15;
    int m0 = ty * 4, n0 = tx * 4;
    int x2off = x1off ^ 32;

    // Load + normalize into transposed smem tile
#pragma unroll
    for (int i = 0; i < 16; i++) {
        int idx = tid + i * 256;
        int m = idx >> 6, c = idx & 63;
        float v = xin[(size_t)(mb + m) * DIM + c];
        xT[c * LDT + m] = (v - g_mean[c]) * g_rstd[c];
    }
    __syncthreads();

    float sreg[4][2];
#pragma unroll 1
    for (int pass = 0; pass < 2; pass++) {
        const float* W1 = pass ? tW1 : sW1;
        const float* B1 = pass ? tb1 : sb1;
        const float* W2 = pass ? tW2 : sW2;
        const float* B2 = pass ? tb2 : sb2;
        const float* W3 = pass ? tW3 : sW3;
        const float* B3 = pass ? tb3 : sb3;

        // ---- GEMM1: h1 = relu(x1 @ W1^T + b1), K=32 ----
        for (int nc = 0; nc < 8; nc++) {
            __syncthreads();
#pragma unroll
            for (int i = 0; i < 8; i++) {
                int idx = tid + i * 256;
                int n = idx >> 5, k = idx & 31;
                wpan[k * LDT + n] = W1[(nc * 64 + n) * DH + k];
            }
            __syncthreads();
            float acc[4][4] = {};
            mm_tile32(xT + x1off * LDT, wpan, acc, m0, n0);
#pragma unroll
            for (int j = 0; j < 4; j++) {
                int n = nc * 64 + n0 + j;
                float bb = B1[n];
                float4 r;
                r.x = fmaxf(acc[0][j] + bb, 0.f);
                r.y = fmaxf(acc[1][j] + bb, 0.f);
                r.z = fmaxf(acc[2][j] + bb, 0.f);
                r.w = fmaxf(acc[3][j] + bb, 0.f);
                *(float4*)(h1T + n * LDT + m0) = r;
            }
        }
        __syncthreads();

        // ---- GEMM2 (K=512, panel-staged) + GEMM3 (accumulated) ----
        float g3[4][2] = {};
        for (int nc = 0; nc < 8; nc++) {
            float acc[4][4] = {};
            for (int k0 = 0; k0 < HID; k0 += 32) {
                __syncthreads();
#pragma unroll
                for (int i = 0; i < 8; i++) {
                    int idx = tid + i * 256;
                    int n = idx >> 5, k = idx & 31;
                    wpan[k * LDT + n] = W2[(size_t)(nc * 64 + n) * HID + (k0 + k)];
                }
                __syncthreads();
                mm_tile32(h1T + k0 * LDT, wpan, acc, m0, n0);
            }
            // h2 chunk = relu(acc + b2)  -> h2cT[n_local][m]
#pragma unroll
            for (int j = 0; j < 4; j++) {
                int n = nc * 64 + n0 + j;
                float bb = B2[n];
                float4 r;
                r.x = fmaxf(acc[0][j] + bb, 0.f);
                r.y = fmaxf(acc[1][j] + bb, 0.f);
                r.z = fmaxf(acc[2][j] + bb, 0.f);
                r.w = fmaxf(acc[3][j] + bb, 0.f);
                *(float4*)(h2cT + (n0 + j) * LDT + m0) = r;
            }
            // stage W3 panel [n_local][j]
#pragma unroll
            for (int i = 0; i < 8; i++) {
                int idx = tid + i * 256;
                int j = idx >> 6, n = idx & 63;
                w3t[n * 34 + j] = W3[(size_t)j * HID + nc * 64 + n];
            }
            __syncthreads();
            // GEMM3 partial: out[m][j] += h2c[m][n] * W3[j][n]
            int j0 = tx * 2;
#pragma unroll 8
            for (int n = 0; n < 64; n++) {
                float4 a = *(const float4*)(h2cT + n * LDT + m0);
                float2 b = *(const float2*)(w3t + n * 34 + j0);
                g3[0][0] += a.x * b.x; g3[0][1] += a.x * b.y;
                g3[1][0] += a.y * b.x; g3[1][1] += a.y * b.y;
                g3[2][0] += a.z * b.x; g3[2][1] += a.z * b.y;
                g3[3][0] += a.w * b.x; g3[3][1] += a.w * b.y;
            }
            __syncthreads();
        }

        if (pass == 0) {
            // s = g3 + b3; keep in regs for the affine, stash in smem for det
#pragma unroll
            for (int i = 0; i < 4; i++)
#pragma unroll
                for (int jj = 0; jj < 2; jj++) {
                    float sv = g3[i][jj] + B3[tx * 2 + jj];
                    sreg[i][jj] = sv;
                    sbuf[(m0 + i) * 33 + tx * 2 + jj] = sv;
                }
            __syncthreads();
            if (tid < TM) {
                float ds = 0.f;
#pragma unroll
                for (int j = 0; j < DH; j++) ds += sbuf[tid * 33 + j];
                if (first) g_det[mb + tid] = ds;
                else       g_det[mb + tid] += ds;
            }
        } else {
            // y2 = x2 * exp(s) + t ; new x = [x1, y2]
#pragma unroll
            for (int i = 0; i < 4; i++) {
                int m = m0 + i;
#pragma unroll
                for (int jj = 0; jj < 2; jj++) {
                    int j = tx * 2 + jj;
                    float tv  = g3[i][jj] + B3[j];
                    float x2v = xT[(x2off + j) * LDT + m];
                    float y2  = x2v * expf(sreg[i][jj]) + tv;
                    g_x[(size_t)(mb + m) * DIM + DH + j] = y2;
                    g_x[(size_t)(mb + m) * DIM + j]      = xT[(x1off + j) * LDT + m];
                }
            }
        }
    }
}

// ---------------------------------------------------------------------------
// Finalize: copy y, per-row log_likelihood, det copy, block partial sums.
// Output layout (flattened tuple): y | loss | ll | det_s | ll_mean | det_mean
// ---------------------------------------------------------------------------
#define OFF_LOSS   (NR * DIM)
#define OFF_LL     (NR * DIM + 1)
#define OFF_DET    (NR * DIM + 1 + NR)
#define OFF_LLM    (NR * DIM + 1 + 2 * NR)
#define OFF_DETM   (NR * DIM + 2 + 2 * NR)

__global__ void finalize_kernel(float* __restrict__ out, int out_size) {
    __shared__ float tile[TM][DIM + 1];
    __shared__ float red[TM];
    int tid = threadIdx.x;
    int mb = blockIdx.x * TM;
#pragma unroll
    for (int i = 0; i < 16; i++) {
        int idx = tid + i * 256;
        int m = idx >> 6, c = idx & 63;
        float v = g_x[(size_t)(mb + m) * DIM + c];
        tile[m][c] = v;
        int o = (mb + m) * DIM + c;
        if (o < out_size) out[o] = v;
    }
    __syncthreads();
    if (tid < TM) {
        float ss = 0.f;
#pragma unroll
        for (int c = 0; c < DIM; c++) { float v = tile[tid][c]; ss += v * v; }
        float ll = -0.5f * ss - 58.81206612509906f;  // 32*ln(2*pi)
        int o1 = OFF_LL + mb + tid;
        if (o1 < out_size) out[o1] = ll;
        int o2 = OFF_DET + mb + tid;
        if (o2 < out_size) out[o2] = g_det[mb + tid];
        red[tid] = ll;
    }
    __syncthreads();
    if (tid == 0) {
        float s = 0.f;
        for (int k = 0; k < TM; k++) s += red[k];
        g_llp[blockIdx.x] = s;
    }
    if (tid == 32) {
        float s = 0.f;
        for (int k = 0; k < TM; k++) s += g_det[mb + k];
        g_detp[blockIdx.x] = s;
    }
}

__global__ void final_reduce_kernel(float* __restrict__ out, int out_size) {
    __shared__ float A[256], B[256];
    int t = threadIdx.x;
    float s1 = 0.f, s2 = 0.f;
    for (int i = 0; i < NBLK / 256; i++) {
        s1 += g_llp[t + i * 256];
        s2 += g_detp[t + i * 256];
    }
    A[t] = s1; B[t] = s2;
    __syncthreads();
    for (int off = 128; off > 0; off >>= 1) {
        if (t < off) { A[t] += A[t + off]; B[t] += B[t + off]; }
        __syncthreads();
    }
    if (t == 0) {
        float llm = A[0] / (float)NR;
        float dm  = B[0] / (float)NR;
        if (OFF_LOSS < out_size) out[OFF_LOSS] = -(dm + llm);
        if (OFF_LLM  < out_size) out[OFF_LLM]  = llm;
        if (OFF_DETM < out_size) out[OFF_DETM] = dm;
    }
}

// ---------------------------------------------------------------------------
extern "C" void kernel_launch(void* const* d_in, const int* in_sizes, int n_in,
                              void* d_out, int out_size) {
    const float* x   = (const float*)d_in[0];
    const float* sW1 = (const float*)d_in[1];
    const float* sb1 = (const float*)d_in[2];
    const float* sW2 = (const float*)d_in[3];
    const float* sb2 = (const float*)d_in[4];
    const float* sW3 = (const float*)d_in[5];
    const float* sb3 = (const float*)d_in[6];
    const float* tW1 = (const float*)d_in[7];
    const float* tb1 = (const float*)d_in[8];
    const float* tW2 = (const float*)d_in[9];
    const float* tb2 = (const float*)d_in[10];
    const float* tW3 = (const float*)d_in[11];
    const float* tb3 = (const float*)d_in[12];
    float* out = (float*)d_out;

    cudaFuncSetAttribute(fused_layer,
                         cudaFuncAttributeMaxDynamicSharedMemorySize, SMEM_BYTES);

    for (int l = 0; l < NLAYERS; l++) {
        int use_ext = (l == 0) ? 1 : 0;
        stats_partial<<<256, 256>>>(x, use_ext);
        stats_final<<<1, 64>>>();
        fused_layer<<<NBLK, 256, SMEM_BYTES>>>(
            x, use_ext, (l & 1) ? 32 : 0, (l == 0) ? 1 : 0,
            sW1 + (size_t)l * HID * DH, sb1 + (size_t)l * HID,
            sW2 + (size_t)l * HID * HID, sb2 + (size_t)l * HID,
            sW3 + (size_t)l * DH * HID, sb3 + (size_t)l * DH,
            tW1 + (size_t)l * HID * DH, tb1 + (size_t)l * HID,
            tW2 + (size_t)l * HID * HID, tb2 + (size_t)l * HID,
            tW3 + (size_t)l * DH * HID, tb3 + (size_t)l * DH);
    }
    finalize_kernel<<<NBLK, 256>>>(out, out_size);
    final_reduce_kernel<<<1, 256>>>(out, out_size);
}